// round 1
// baseline (speedup 1.0000x reference)
#include <cuda_runtime.h>
#include <cuda_bf16.h>

// Problem constants
constexpr int BATCH = 4;
constexpr int SEQ   = 2048;
constexpr int DIM   = 1024;   // d_in == d_out
constexpr int MTOT  = BATCH * SEQ;  // 8192

// Scratch (static device memory; allocation APIs are forbidden)
__device__ float g_q[(size_t)BATCH * SEQ * DIM];
__device__ float g_k[(size_t)BATCH * SEQ * DIM];
__device__ float g_v[(size_t)BATCH * SEQ * DIM];
__device__ float g_p[(size_t)BATCH * SEQ * SEQ];   // scores -> probabilities

// Tiling
constexpr int BM = 128, BN = 128, BK = 16;
constexpr int TM = 8,   TN = 8;
constexpr int NTHREADS = 256;

// ---------------------------------------------------------------------------
// NT GEMM body: C[m,n] (+)= scale * sum_k A[m,k] * B[n,k]
// A: [M,K] row-major (k contiguous), B: [N,K] row-major (k contiguous)
// All dims multiples of tile sizes; no bounds checks needed.
// ---------------------------------------------------------------------------
__device__ __forceinline__ void gemm_nt_tile(
    const float* __restrict__ A, const float* __restrict__ B, float* __restrict__ C,
    int ldc, int K, int m0, int n0, float scale)
{
    __shared__ float As[BK][BM];
    __shared__ float Bs[BK][BN];

    const int tid = threadIdx.x;
    const int tm = tid >> 4;       // 0..15
    const int tn = tid & 15;       // 0..15

    float acc[TM][TN];
    #pragma unroll
    for (int i = 0; i < TM; ++i)
        #pragma unroll
        for (int j = 0; j < TN; ++j) acc[i][j] = 0.f;

    for (int kt = 0; kt < K; kt += BK) {
        // Load A tile (128 rows x 16 k), transposed into As[k][m]
        #pragma unroll
        for (int it = 0; it < 2; ++it) {
            int idx = tid + it * NTHREADS;          // 0..511
            int row = idx >> 2;                     // 0..127
            int kq  = (idx & 3) << 2;               // 0,4,8,12
            float4 v = *reinterpret_cast<const float4*>(
                &A[(size_t)(m0 + row) * K + kt + kq]);
            As[kq + 0][row] = v.x; As[kq + 1][row] = v.y;
            As[kq + 2][row] = v.z; As[kq + 3][row] = v.w;
        }
        // Load B tile (128 rows x 16 k), transposed into Bs[k][n]
        #pragma unroll
        for (int it = 0; it < 2; ++it) {
            int idx = tid + it * NTHREADS;
            int row = idx >> 2;
            int kq  = (idx & 3) << 2;
            float4 v = *reinterpret_cast<const float4*>(
                &B[(size_t)(n0 + row) * K + kt + kq]);
            Bs[kq + 0][row] = v.x; Bs[kq + 1][row] = v.y;
            Bs[kq + 2][row] = v.z; Bs[kq + 3][row] = v.w;
        }
        __syncthreads();

        #pragma unroll
        for (int kk = 0; kk < BK; ++kk) {
            float4 a0 = *reinterpret_cast<const float4*>(&As[kk][tm * TM]);
            float4 a1 = *reinterpret_cast<const float4*>(&As[kk][tm * TM + 4]);
            float4 b0 = *reinterpret_cast<const float4*>(&Bs[kk][tn * TN]);
            float4 b1 = *reinterpret_cast<const float4*>(&Bs[kk][tn * TN + 4]);
            float a[TM] = {a0.x, a0.y, a0.z, a0.w, a1.x, a1.y, a1.z, a1.w};
            float b[TN] = {b0.x, b0.y, b0.z, b0.w, b1.x, b1.y, b1.z, b1.w};
            #pragma unroll
            for (int i = 0; i < TM; ++i)
                #pragma unroll
                for (int j = 0; j < TN; ++j)
                    acc[i][j] = fmaf(a[i], b[j], acc[i][j]);
        }
        __syncthreads();
    }

    #pragma unroll
    for (int i = 0; i < TM; ++i) {
        float* crow = &C[(size_t)(m0 + tm * TM + i) * ldc + n0 + tn * TN];
        float4 o0 = make_float4(acc[i][0] * scale, acc[i][1] * scale,
                                acc[i][2] * scale, acc[i][3] * scale);
        float4 o1 = make_float4(acc[i][4] * scale, acc[i][5] * scale,
                                acc[i][6] * scale, acc[i][7] * scale);
        *reinterpret_cast<float4*>(crow)     = o0;
        *reinterpret_cast<float4*>(crow + 4) = o1;
    }
}

// ---------------------------------------------------------------------------
// Kernel 1: QKV projections. C = X @ W^T.  grid: (DIM/BN, MTOT/BM, 3)
// ---------------------------------------------------------------------------
__global__ __launch_bounds__(NTHREADS)
void qkv_kernel(const float* __restrict__ x,
                const float* __restrict__ wq,
                const float* __restrict__ wk,
                const float* __restrict__ wv)
{
    const float* W = (blockIdx.z == 0) ? wq : (blockIdx.z == 1) ? wk : wv;
    float* C = (blockIdx.z == 0) ? g_q : (blockIdx.z == 1) ? g_k : g_v;
    const int m0 = blockIdx.y * BM;
    const int n0 = blockIdx.x * BN;
    gemm_nt_tile(x, W, C, DIM, DIM, m0, n0, 1.0f);
}

// ---------------------------------------------------------------------------
// Kernel 2: scores = (Q @ K^T) / 32, lower-triangular tiles only.
// grid: (SEQ/BN, SEQ/BM, BATCH)
// ---------------------------------------------------------------------------
__global__ __launch_bounds__(NTHREADS)
void scores_kernel()
{
    const int m0 = blockIdx.y * BM;
    const int n0 = blockIdx.x * BN;
    if (n0 >= m0 + BM) return;             // tile entirely above the diagonal
    const int b = blockIdx.z;
    const float* Q = g_q + (size_t)b * SEQ * DIM;
    const float* K = g_k + (size_t)b * SEQ * DIM;
    float* P = g_p + (size_t)b * SEQ * SEQ;
    gemm_nt_tile(Q, K, P, SEQ, DIM, m0, n0, 0.03125f /* 1/sqrt(1024) */);
}

// ---------------------------------------------------------------------------
// Kernel 3: row softmax over j <= i; writes 0 for j > i (enables plain GEMM).
// grid: (BATCH*SEQ), 256 threads per row.
// ---------------------------------------------------------------------------
__global__ __launch_bounds__(NTHREADS)
void softmax_kernel()
{
    const int tid = threadIdx.x;
    const int row = blockIdx.x;
    const int b = row >> 11;               // /SEQ
    const int i = row & (SEQ - 1);
    float* p = g_p + (size_t)b * SEQ * SEQ + (size_t)i * SEQ;
    const int n = i + 1;

    __shared__ float sbuf[SEQ];
    __shared__ float sred[NTHREADS / 32];

    for (int j = tid; j < n; j += NTHREADS) sbuf[j] = p[j];
    __syncthreads();

    float lv[SEQ / NTHREADS];              // up to 8 elements per thread
    int cnt = 0;
    float m = -3.4e38f;
    for (int j = tid; j < n; j += NTHREADS) {
        float xv = sbuf[j];
        lv[cnt++] = xv;
        m = fmaxf(m, xv);
    }
    #pragma unroll
    for (int o = 16; o > 0; o >>= 1) m = fmaxf(m, __shfl_xor_sync(0xffffffffu, m, o));
    if ((tid & 31) == 0) sred[tid >> 5] = m;
    __syncthreads();
    float rowmax = sred[0];
    #pragma unroll
    for (int w = 1; w < NTHREADS / 32; ++w) rowmax = fmaxf(rowmax, sred[w]);
    __syncthreads();

    float s = 0.f;
    for (int t = 0; t < cnt; ++t) {
        float e = __expf(lv[t] - rowmax);
        lv[t] = e;
        s += e;
    }
    #pragma unroll
    for (int o = 16; o > 0; o >>= 1) s += __shfl_xor_sync(0xffffffffu, s, o);
    if ((tid & 31) == 0) sred[tid >> 5] = s;
    __syncthreads();
    float rowsum = 0.f;
    #pragma unroll
    for (int w = 0; w < NTHREADS / 32; ++w) rowsum += sred[w];
    const float inv = 1.0f / rowsum;

    int t = 0;
    for (int j = tid; j < SEQ; j += NTHREADS) {
        p[j] = (j < n) ? lv[t++] * inv : 0.0f;
    }
}

// ---------------------------------------------------------------------------
// Kernel 4: out = P @ V (NN GEMM), K-loop truncated at m0+BM (causality).
// grid: (DIM/BN, SEQ/BM, BATCH)
// ---------------------------------------------------------------------------
__global__ __launch_bounds__(NTHREADS)
void pv_kernel(float* __restrict__ out)
{
    const int b = blockIdx.z;
    const int m0 = blockIdx.y * BM;
    const int n0 = blockIdx.x * BN;
    const float* A = g_p + (size_t)b * SEQ * SEQ;   // [SEQ, SEQ], k contiguous
    const float* Bv = g_v + (size_t)b * SEQ * DIM;  // [SEQ, DIM], n contiguous
    float* C = out + (size_t)b * SEQ * DIM;

    __shared__ float As[BK][BM];
    __shared__ float Bs[BK][BN];

    const int tid = threadIdx.x;
    const int tm = tid >> 4;
    const int tn = tid & 15;

    float acc[TM][TN];
    #pragma unroll
    for (int i = 0; i < TM; ++i)
        #pragma unroll
        for (int j = 0; j < TN; ++j) acc[i][j] = 0.f;

    const int kend = m0 + BM;              // all P[i][j]=0 for j>i; stop at tile end

    for (int kt = 0; kt < kend; kt += BK) {
        // A tile (P): 128 rows x 16 k, transposed
        #pragma unroll
        for (int it = 0; it < 2; ++it) {
            int idx = tid + it * NTHREADS;
            int row = idx >> 2;
            int kq  = (idx & 3) << 2;
            float4 v = *reinterpret_cast<const float4*>(
                &A[(size_t)(m0 + row) * SEQ + kt + kq]);
            As[kq + 0][row] = v.x; As[kq + 1][row] = v.y;
            As[kq + 2][row] = v.z; As[kq + 3][row] = v.w;
        }
        // B tile (V): 16 k-rows x 128 n, direct copy
        #pragma unroll
        for (int it = 0; it < 2; ++it) {
            int idx = tid + it * NTHREADS;
            int row = idx >> 5;                     // 0..15
            int cq  = (idx & 31) << 2;              // 0..124 step 4
            float4 v = *reinterpret_cast<const float4*>(
                &Bv[(size_t)(kt + row) * DIM + n0 + cq]);
            *reinterpret_cast<float4*>(&Bs[row][cq]) = v;
        }
        __syncthreads();

        #pragma unroll
        for (int kk = 0; kk < BK; ++kk) {
            float4 a0 = *reinterpret_cast<const float4*>(&As[kk][tm * TM]);
            float4 a1 = *reinterpret_cast<const float4*>(&As[kk][tm * TM + 4]);
            float4 b0 = *reinterpret_cast<const float4*>(&Bs[kk][tn * TN]);
            float4 b1 = *reinterpret_cast<const float4*>(&Bs[kk][tn * TN + 4]);
            float a[TM] = {a0.x, a0.y, a0.z, a0.w, a1.x, a1.y, a1.z, a1.w};
            float b[TN] = {b0.x, b0.y, b0.z, b0.w, b1.x, b1.y, b1.z, b1.w};
            #pragma unroll
            for (int i = 0; i < TM; ++i)
                #pragma unroll
                for (int j = 0; j < TN; ++j)
                    acc[i][j] = fmaf(a[i], b[j], acc[i][j]);
        }
        __syncthreads();
    }

    #pragma unroll
    for (int i = 0; i < TM; ++i) {
        float* crow = &C[(size_t)(m0 + tm * TM + i) * DIM + n0 + tn * TN];
        float4 o0 = make_float4(acc[i][0], acc[i][1], acc[i][2], acc[i][3]);
        float4 o1 = make_float4(acc[i][4], acc[i][5], acc[i][6], acc[i][7]);
        *reinterpret_cast<float4*>(crow)     = o0;
        *reinterpret_cast<float4*>(crow + 4) = o1;
    }
}

// ---------------------------------------------------------------------------
extern "C" void kernel_launch(void* const* d_in, const int* in_sizes, int n_in,
                              void* d_out, int out_size)
{
    const float* x  = (const float*)d_in[0];
    const float* wq = (const float*)d_in[1];
    const float* wk = (const float*)d_in[2];
    const float* wv = (const float*)d_in[3];
    float* out = (float*)d_out;

    {
        dim3 grid(DIM / BN, MTOT / BM, 3);
        qkv_kernel<<<grid, NTHREADS>>>(x, wq, wk, wv);
    }
    {
        dim3 grid(SEQ / BN, SEQ / BM, BATCH);
        scores_kernel<<<grid, NTHREADS>>>();
    }
    {
        softmax_kernel<<<BATCH * SEQ, NTHREADS>>>();
    }
    {
        dim3 grid(DIM / BN, SEQ / BM, BATCH);
        pv_kernel<<<grid, NTHREADS>>>(out);
    }
}

// round 3
// speedup vs baseline: 2.3586x; 2.3586x over previous
#include <cuda_runtime.h>
#include <cuda_bf16.h>
#include <cstdint>

// ---------------------------------------------------------------------------
// Problem constants
// ---------------------------------------------------------------------------
constexpr int BATCH = 4;
constexpr int SEQ   = 2048;
constexpr int DIM   = 1024;
constexpr int MTOT  = BATCH * SEQ;   // 8192

// ---------------------------------------------------------------------------
// Static device scratch
// ---------------------------------------------------------------------------
__device__ __nv_bfloat16 g_xh[(size_t)MTOT * DIM];
__device__ __nv_bfloat16 g_xl[(size_t)MTOT * DIM];
__device__ __nv_bfloat16 g_wh[(size_t)3 * DIM * DIM];
__device__ __nv_bfloat16 g_wl[(size_t)3 * DIM * DIM];
__device__ __nv_bfloat16 g_qh[(size_t)MTOT * DIM];
__device__ __nv_bfloat16 g_ql[(size_t)MTOT * DIM];
__device__ __nv_bfloat16 g_kh[(size_t)MTOT * DIM];
__device__ __nv_bfloat16 g_kl[(size_t)MTOT * DIM];
__device__ __nv_bfloat16 g_vh[(size_t)MTOT * DIM];
__device__ __nv_bfloat16 g_vl[(size_t)MTOT * DIM];
__device__ float         g_s [(size_t)BATCH * SEQ * SEQ];
__device__ __nv_bfloat16 g_ph[(size_t)BATCH * SEQ * SEQ];
__device__ __nv_bfloat16 g_pl[(size_t)BATCH * SEQ * SEQ];

// ---------------------------------------------------------------------------
// Tiling
// ---------------------------------------------------------------------------
constexpr int NTH = 256;                  // 8 warps: 2 (m) x 4 (n)
constexpr int ROWB_A  = 80;               // 32 bf16 = 64B + 16B pad (bank-safe)
constexpr int ATILE   = 128 * ROWB_A;     // 10240 B
constexpr int ROWB_V  = 272;              // 128 bf16 = 256B + 16B pad
constexpr int VTILE   = 32 * ROWB_V;      // 8704 B
constexpr int STAGE_NT = 4 * ATILE;               // Ah, Al, Bh, Bl
constexpr int SMEM_NT  = 2 * STAGE_NT;            // 81920
constexpr int STAGE_PV = 2 * ATILE + 2 * VTILE;   // Ph, Pl, Vh, Vl = 37888
constexpr int SMEM_PV  = 2 * STAGE_PV;            // 75776

// ---------------------------------------------------------------------------
// PTX helpers (base sm_103-legal only: cp.async, ldmatrix, mma.sync)
// ---------------------------------------------------------------------------
__device__ __forceinline__ uint32_t smem_u32(const void* p) {
    uint32_t a;
    asm("{ .reg .u64 t; cvta.to.shared.u64 t, %1; cvt.u32.u64 %0, t; }"
        : "=r"(a) : "l"(p));
    return a;
}
#define CP16(dst, src) \
    asm volatile("cp.async.cg.shared.global [%0], [%1], 16;" :: "r"(dst), "l"(src))
#define CP_COMMIT() asm volatile("cp.async.commit_group;" ::: "memory")
#define CP_WAIT0()  asm volatile("cp.async.wait_group 0;" ::: "memory")
#define CP_WAIT1()  asm volatile("cp.async.wait_group 1;" ::: "memory")

#define LDSM4(r, a) asm volatile( \
    "ldmatrix.sync.aligned.m8n8.x4.shared.b16 {%0,%1,%2,%3}, [%4];" \
    : "=r"((r)[0]), "=r"((r)[1]), "=r"((r)[2]), "=r"((r)[3]) : "r"(a))
#define LDSM2(r, a) asm volatile( \
    "ldmatrix.sync.aligned.m8n8.x2.shared.b16 {%0,%1}, [%2];" \
    : "=r"((r)[0]), "=r"((r)[1]) : "r"(a))
#define LDSM2T(r, a) asm volatile( \
    "ldmatrix.sync.aligned.m8n8.x2.trans.shared.b16 {%0,%1}, [%2];" \
    : "=r"((r)[0]), "=r"((r)[1]) : "r"(a))

__device__ __forceinline__ void mma_bf16(float* d, const uint32_t* a, const uint32_t* b) {
    asm volatile(
        "mma.sync.aligned.m16n8k16.row.col.f32.bf16.bf16.f32 "
        "{%0,%1,%2,%3}, {%4,%5,%6,%7}, {%8,%9}, {%0,%1,%2,%3};"
        : "+f"(d[0]), "+f"(d[1]), "+f"(d[2]), "+f"(d[3])
        : "r"(a[0]), "r"(a[1]), "r"(a[2]), "r"(a[3]), "r"(b[0]), "r"(b[1]));
}

// ---------------------------------------------------------------------------
// Stage loaders (256 threads). NT: 128 rows x 32 bf16, K-contiguous source.
// ---------------------------------------------------------------------------
__device__ __forceinline__ void load_nt(uint32_t sdst, const __nv_bfloat16* src,
                                        int ld, int kt) {
    const int tid = threadIdx.x;
    #pragma unroll
    for (int it = 0; it < 2; ++it) {
        int idx = it * NTH + tid;      // 0..511
        int row = idx >> 2, seg = idx & 3;
        CP16(sdst + row * ROWB_A + seg * 16,
             src + (size_t)row * ld + kt + seg * 8);
    }
}
// V: 32 rows (k) x 128 cols (n), n-contiguous source (ld = DIM), src pre-offset by n0.
__device__ __forceinline__ void load_v(uint32_t sdst, const __nv_bfloat16* src, int kt) {
    const int tid = threadIdx.x;
    #pragma unroll
    for (int it = 0; it < 2; ++it) {
        int idx = it * NTH + tid;      // 0..511
        int row = idx >> 4, seg = idx & 15;
        CP16(sdst + row * ROWB_V + seg * 16,
             src + (size_t)(kt + row) * DIM + seg * 8);
    }
}

// ---------------------------------------------------------------------------
// NT mainloop: acc[4][4][4] += A[128xK] * B[128xK]^T   (bf16x3 emulation)
// ---------------------------------------------------------------------------
__device__ __forceinline__ void mainloop_nt(
    const __nv_bfloat16* Ah, const __nv_bfloat16* Al, int lda,
    const __nv_bfloat16* Bh, const __nv_bfloat16* Bl, int ldb,
    int nstages, char* smem, float (&acc)[4][4][4])
{
    const int tid = threadIdx.x, lane = tid & 31, wid = tid >> 5;
    const int wm = (wid >> 2) * 64, wn = (wid & 3) * 32;
    const uint32_t sb = smem_u32(smem);
    const uint32_t aoff = (lane & 15) * ROWB_A + (lane >> 4) * 16;
    const uint32_t boff = (lane & 7) * ROWB_A + ((lane >> 3) & 1) * 16;

    // prologue
    {
        load_nt(sb,             Ah, lda, 0);
        load_nt(sb + ATILE,     Al, lda, 0);
        load_nt(sb + 2 * ATILE, Bh, ldb, 0);
        load_nt(sb + 3 * ATILE, Bl, ldb, 0);
        CP_COMMIT();
    }
    for (int s = 0; s < nstages; ++s) {
        if (s + 1 < nstages) {
            uint32_t st = sb + ((s + 1) & 1) * STAGE_NT;
            int kt = (s + 1) * 32;
            load_nt(st,             Ah, lda, kt);
            load_nt(st + ATILE,     Al, lda, kt);
            load_nt(st + 2 * ATILE, Bh, ldb, kt);
            load_nt(st + 3 * ATILE, Bl, ldb, kt);
            CP_COMMIT();
            CP_WAIT1();
        } else {
            CP_WAIT0();
        }
        __syncthreads();
        const uint32_t st = sb + (s & 1) * STAGE_NT;
        #pragma unroll
        for (int k16 = 0; k16 < 2; ++k16) {
            uint32_t ah[4][4], al[4][4], bh[4][2], bl[4][2];
            #pragma unroll
            for (int mb = 0; mb < 4; ++mb) {
                uint32_t ad = st + (wm + mb * 16) * ROWB_A + k16 * 32 + aoff;
                LDSM4(ah[mb], ad);
                LDSM4(al[mb], ad + ATILE);
            }
            #pragma unroll
            for (int nb = 0; nb < 4; ++nb) {
                uint32_t bd = st + 2 * ATILE + (wn + nb * 8) * ROWB_A + k16 * 32 + boff;
                LDSM2(bh[nb], bd);
                LDSM2(bl[nb], bd + ATILE);
            }
            #pragma unroll
            for (int mb = 0; mb < 4; ++mb)
                #pragma unroll
                for (int nb = 0; nb < 4; ++nb) {
                    mma_bf16(acc[mb][nb], ah[mb], bh[nb]);
                    mma_bf16(acc[mb][nb], ah[mb], bl[nb]);
                    mma_bf16(acc[mb][nb], al[mb], bh[nb]);
                }
        }
        __syncthreads();
    }
}

// ---------------------------------------------------------------------------
// PV mainloop: A = P (NT, k-contig), B = V (k-major, ldmatrix.trans)
// ---------------------------------------------------------------------------
__device__ __forceinline__ void mainloop_pv(
    const __nv_bfloat16* Ah, const __nv_bfloat16* Al,
    const __nv_bfloat16* Vh, const __nv_bfloat16* Vl,   // pre-offset by n0
    int nstages, char* smem, float (&acc)[4][4][4])
{
    const int tid = threadIdx.x, lane = tid & 31, wid = tid >> 5;
    const int wm = (wid >> 2) * 64, wn = (wid & 3) * 32;
    const uint32_t sb = smem_u32(smem);
    const uint32_t aoff  = (lane & 15) * ROWB_A + (lane >> 4) * 16;
    const uint32_t boffv = ((lane & 7) + ((lane >> 3) & 1) * 8) * ROWB_V;
    constexpr int VOFF = 2 * ATILE;

    {
        load_nt(sb,         Ah, SEQ, 0);
        load_nt(sb + ATILE, Al, SEQ, 0);
        load_v(sb + VOFF,         Vh, 0);
        load_v(sb + VOFF + VTILE, Vl, 0);
        CP_COMMIT();
    }
    for (int s = 0; s < nstages; ++s) {
        if (s + 1 < nstages) {
            uint32_t st = sb + ((s + 1) & 1) * STAGE_PV;
            int kt = (s + 1) * 32;
            load_nt(st,         Ah, SEQ, kt);
            load_nt(st + ATILE, Al, SEQ, kt);
            load_v(st + VOFF,         Vh, kt);
            load_v(st + VOFF + VTILE, Vl, kt);
            CP_COMMIT();
            CP_WAIT1();
        } else {
            CP_WAIT0();
        }
        __syncthreads();
        const uint32_t st = sb + (s & 1) * STAGE_PV;
        #pragma unroll
        for (int k16 = 0; k16 < 2; ++k16) {
            uint32_t ah[4][4], al[4][4], bh[4][2], bl[4][2];
            #pragma unroll
            for (int mb = 0; mb < 4; ++mb) {
                uint32_t ad = st + (wm + mb * 16) * ROWB_A + k16 * 32 + aoff;
                LDSM4(ah[mb], ad);
                LDSM4(al[mb], ad + ATILE);
            }
            #pragma unroll
            for (int nb = 0; nb < 4; ++nb) {
                uint32_t bd = st + VOFF + k16 * 16 * ROWB_V + boffv + (wn + nb * 8) * 2;
                LDSM2T(bh[nb], bd);
                LDSM2T(bl[nb], bd + VTILE);
            }
            #pragma unroll
            for (int mb = 0; mb < 4; ++mb)
                #pragma unroll
                for (int nb = 0; nb < 4; ++nb) {
                    mma_bf16(acc[mb][nb], ah[mb], bh[nb]);
                    mma_bf16(acc[mb][nb], ah[mb], bl[nb]);
                    mma_bf16(acc[mb][nb], al[mb], bh[nb]);
                }
        }
        __syncthreads();
    }
}

// ---------------------------------------------------------------------------
// Kernel 1: QKV projection. grid (8, 64, 3)
// ---------------------------------------------------------------------------
__global__ __launch_bounds__(NTH, 1)
void qkv_gemm()
{
    extern __shared__ char smem[];
    const int z  = blockIdx.z;
    const int n0 = blockIdx.x * 128;
    const int m0 = blockIdx.y * 128;
    const int lane = threadIdx.x & 31, wid = threadIdx.x >> 5;
    const int wm = (wid >> 2) * 64, wn = (wid & 3) * 32;

    float acc[4][4][4];
    #pragma unroll
    for (int i = 0; i < 4; ++i)
        #pragma unroll
        for (int j = 0; j < 4; ++j)
            #pragma unroll
            for (int r = 0; r < 4; ++r) acc[i][j][r] = 0.f;

    const __nv_bfloat16* Ah = g_xh + (size_t)m0 * DIM;
    const __nv_bfloat16* Al = g_xl + (size_t)m0 * DIM;
    const __nv_bfloat16* Bh = g_wh + (size_t)z * DIM * DIM + (size_t)n0 * DIM;
    const __nv_bfloat16* Bl = g_wl + (size_t)z * DIM * DIM + (size_t)n0 * DIM;
    mainloop_nt(Ah, Al, DIM, Bh, Bl, DIM, DIM / 32, smem, acc);

    const float scale = (z == 0) ? 0.03125f : 1.0f;   // fold 1/sqrt(D) into Q
    __nv_bfloat16* dh = (z == 0) ? g_qh : (z == 1) ? g_kh : g_vh;
    __nv_bfloat16* dl = (z == 0) ? g_ql : (z == 1) ? g_kl : g_vl;

    #pragma unroll
    for (int mb = 0; mb < 4; ++mb)
        #pragma unroll
        for (int rh = 0; rh < 2; ++rh) {
            const int row = m0 + wm + mb * 16 + (lane >> 2) + rh * 8;
            #pragma unroll
            for (int nb = 0; nb < 4; ++nb) {
                const int col = n0 + wn + nb * 8 + (lane & 3) * 2;
                float v0 = acc[mb][nb][rh * 2 + 0] * scale;
                float v1 = acc[mb][nb][rh * 2 + 1] * scale;
                __nv_bfloat16 h0 = __float2bfloat16(v0);
                __nv_bfloat16 h1 = __float2bfloat16(v1);
                __nv_bfloat16 l0 = __float2bfloat16(v0 - __bfloat162float(h0));
                __nv_bfloat16 l1 = __float2bfloat16(v1 - __bfloat162float(h1));
                *(uint32_t*)(dh + (size_t)row * DIM + col) =
                    (uint32_t)__bfloat16_as_ushort(h0) |
                    ((uint32_t)__bfloat16_as_ushort(h1) << 16);
                *(uint32_t*)(dl + (size_t)row * DIM + col) =
                    (uint32_t)__bfloat16_as_ushort(l0) |
                    ((uint32_t)__bfloat16_as_ushort(l1) << 16);
            }
        }
}

// ---------------------------------------------------------------------------
// Kernel 2: scores = Qs @ K^T. grid (16, 16, 4); lower-tri tiles only.
// ---------------------------------------------------------------------------
__global__ __launch_bounds__(NTH, 1)
void scores_gemm()
{
    const int n0 = blockIdx.x * 128;
    const int m0 = blockIdx.y * 128;
    if (n0 > m0) return;
    extern __shared__ char smem[];
    const int b = blockIdx.z;
    const int lane = threadIdx.x & 31, wid = threadIdx.x >> 5;
    const int wm = (wid >> 2) * 64, wn = (wid & 3) * 32;

    float acc[4][4][4];
    #pragma unroll
    for (int i = 0; i < 4; ++i)
        #pragma unroll
        for (int j = 0; j < 4; ++j)
            #pragma unroll
            for (int r = 0; r < 4; ++r) acc[i][j][r] = 0.f;

    const size_t rowbase = (size_t)b * SEQ * DIM;
    mainloop_nt(g_qh + rowbase + (size_t)m0 * DIM, g_ql + rowbase + (size_t)m0 * DIM, DIM,
                g_kh + rowbase + (size_t)n0 * DIM, g_kl + rowbase + (size_t)n0 * DIM, DIM,
                DIM / 32, smem, acc);

    float* dst = g_s + (size_t)b * SEQ * SEQ;
    #pragma unroll
    for (int mb = 0; mb < 4; ++mb)
        #pragma unroll
        for (int rh = 0; rh < 2; ++rh) {
            const int row = m0 + wm + mb * 16 + (lane >> 2) + rh * 8;
            #pragma unroll
            for (int nb = 0; nb < 4; ++nb) {
                const int col = n0 + wn + nb * 8 + (lane & 3) * 2;
                *(float2*)(dst + (size_t)row * SEQ + col) =
                    make_float2(acc[mb][nb][rh * 2], acc[mb][nb][rh * 2 + 1]);
            }
        }
}

// ---------------------------------------------------------------------------
// Kernel 3: causal softmax; emits P hi/lo bf16, zeros above diagonal.
// ---------------------------------------------------------------------------
constexpr int SOFT_NTH = 256;
__global__ __launch_bounds__(SOFT_NTH)
void softmax_kernel()
{
    const int tid = threadIdx.x;
    const int row = blockIdx.x;
    const int b = row >> 11;
    const int i = row & (SEQ - 1);
    const float* p = g_s + (size_t)b * SEQ * SEQ + (size_t)i * SEQ;
    __nv_bfloat16* ph = g_ph + (size_t)b * SEQ * SEQ + (size_t)i * SEQ;
    __nv_bfloat16* pl = g_pl + (size_t)b * SEQ * SEQ + (size_t)i * SEQ;
    const int n = i + 1;

    __shared__ float sred[SOFT_NTH / 32];

    float lv[SEQ / SOFT_NTH];
    int cnt = 0;
    float m = -3.4e38f;
    for (int j = tid; j < n; j += SOFT_NTH) {
        float xv = p[j];
        lv[cnt++] = xv;
        m = fmaxf(m, xv);
    }
    #pragma unroll
    for (int o = 16; o > 0; o >>= 1) m = fmaxf(m, __shfl_xor_sync(0xffffffffu, m, o));
    if ((tid & 31) == 0) sred[tid >> 5] = m;
    __syncthreads();
    float rowmax = sred[0];
    #pragma unroll
    for (int w = 1; w < SOFT_NTH / 32; ++w) rowmax = fmaxf(rowmax, sred[w]);
    __syncthreads();

    float s = 0.f;
    for (int t = 0; t < cnt; ++t) {
        float e = __expf(lv[t] - rowmax);
        lv[t] = e;
        s += e;
    }
    #pragma unroll
    for (int o = 16; o > 0; o >>= 1) s += __shfl_xor_sync(0xffffffffu, s, o);
    if ((tid & 31) == 0) sred[tid >> 5] = s;
    __syncthreads();
    float rowsum = 0.f;
    #pragma unroll
    for (int w = 0; w < SOFT_NTH / 32; ++w) rowsum += sred[w];
    const float inv = 1.0f / rowsum;

    int t = 0;
    for (int j = tid; j < SEQ; j += SOFT_NTH) {
        if (j < n) {
            float v = lv[t++] * inv;
            __nv_bfloat16 h = __float2bfloat16(v);
            ph[j] = h;
            pl[j] = __float2bfloat16(v - __bfloat162float(h));
        } else {
            ph[j] = __ushort_as_bfloat16(0);
            pl[j] = __ushort_as_bfloat16(0);
        }
    }
}

// ---------------------------------------------------------------------------
// Kernel 4: out = P @ V. grid (8, 16, 4); K truncated at m0+128.
// ---------------------------------------------------------------------------
__global__ __launch_bounds__(NTH, 1)
void pv_gemm(float* __restrict__ out)
{
    extern __shared__ char smem[];
    const int n0 = blockIdx.x * 128;
    const int m0 = blockIdx.y * 128;
    const int b  = blockIdx.z;
    const int lane = threadIdx.x & 31, wid = threadIdx.x >> 5;
    const int wm = (wid >> 2) * 64, wn = (wid & 3) * 32;

    float acc[4][4][4];
    #pragma unroll
    for (int i = 0; i < 4; ++i)
        #pragma unroll
        for (int j = 0; j < 4; ++j)
            #pragma unroll
            for (int r = 0; r < 4; ++r) acc[i][j][r] = 0.f;

    mainloop_pv(g_ph + (size_t)b * SEQ * SEQ + (size_t)m0 * SEQ,
                g_pl + (size_t)b * SEQ * SEQ + (size_t)m0 * SEQ,
                g_vh + (size_t)b * SEQ * DIM + n0,
                g_vl + (size_t)b * SEQ * DIM + n0,
                (m0 + 128) / 32, smem, acc);

    float* dst = out + (size_t)b * SEQ * DIM;
    #pragma unroll
    for (int mb = 0; mb < 4; ++mb)
        #pragma unroll
        for (int rh = 0; rh < 2; ++rh) {
            const int row = m0 + wm + mb * 16 + (lane >> 2) + rh * 8;
            #pragma unroll
            for (int nb = 0; nb < 4; ++nb) {
                const int col = n0 + wn + nb * 8 + (lane & 3) * 2;
                *(float2*)(dst + (size_t)row * DIM + col) =
                    make_float2(acc[mb][nb][rh * 2], acc[mb][nb][rh * 2 + 1]);
            }
        }
}

// ---------------------------------------------------------------------------
// Kernel 0: split fp32 inputs into bf16 hi/lo
// ---------------------------------------------------------------------------
__global__ __launch_bounds__(256)
void convert_kernel(const float* __restrict__ x,
                    const float* __restrict__ wq,
                    const float* __restrict__ wk,
                    const float* __restrict__ wv)
{
    const size_t NX = (size_t)MTOT * DIM;
    const size_t NW = (size_t)DIM * DIM;
    size_t idx = (size_t)blockIdx.x * 256 + threadIdx.x;
    const size_t total = NX + 3 * NW;
    for (; idx < total; idx += (size_t)gridDim.x * 256) {
        float v;
        __nv_bfloat16 *dh, *dl;
        if (idx < NX) {
            v = x[idx]; dh = &g_xh[idx]; dl = &g_xl[idx];
        } else {
            size_t j = idx - NX;
            size_t z = j / NW, i = j - z * NW;
            v = (z == 0) ? wq[i] : (z == 1) ? wk[i] : wv[i];
            dh = &g_wh[j]; dl = &g_wl[j];
        }
        __nv_bfloat16 h = __float2bfloat16(v);
        *dh = h;
        *dl = __float2bfloat16(v - __bfloat162float(h));
    }
}

// ---------------------------------------------------------------------------
extern "C" void kernel_launch(void* const* d_in, const int* in_sizes, int n_in,
                              void* d_out, int out_size)
{
    const float* x  = (const float*)d_in[0];
    const float* wq = (const float*)d_in[1];
    const float* wk = (const float*)d_in[2];
    const float* wv = (const float*)d_in[3];
    float* out = (float*)d_out;

    cudaFuncSetAttribute(qkv_gemm,    cudaFuncAttributeMaxDynamicSharedMemorySize, SMEM_NT);
    cudaFuncSetAttribute(scores_gemm, cudaFuncAttributeMaxDynamicSharedMemorySize, SMEM_NT);
    cudaFuncSetAttribute(pv_gemm,     cudaFuncAttributeMaxDynamicSharedMemorySize, SMEM_PV);

    convert_kernel<<<2048, 256>>>(x, wq, wk, wv);
    qkv_gemm<<<dim3(8, 64, 3), NTH, SMEM_NT>>>();
    scores_gemm<<<dim3(16, 16, 4), NTH, SMEM_NT>>>();
    softmax_kernel<<<BATCH * SEQ, SOFT_NTH>>>();
    pv_gemm<<<dim3(8, 16, 4), NTH, SMEM_PV>>>(out);
}